// round 7
// baseline (speedup 1.0000x reference)
#include <cuda_runtime.h>
#include <cuda_bf16.h>
#include <math.h>
#include <stdint.h>

#define NPTS     131072
#define HDIM     256
#define PTS      32              // points per CTA (16 per warp-group)
#define NTH      512             // 2 warp-groups x 8 warps
#define NBLK     (NPTS / PTS)    // 4096
#define AP       264             // A smem pitch (bf16): conflict-free ldmatrix
#define KCH      16              // K chunk per pipeline stage
#define NCH      (HDIM / KCH)    // 16 chunks per layer
#define BTILE    (HDIM * KCH)    // bf16 elems per B tile (8192 B)
#define GAMMA_F  (5.0f / 3.0f)

__device__ __align__(16) __nv_bfloat16 g_Wt[2][2][HDIM * HDIM]; // [layer][hi/lo][n*256+k]
__device__ float g_partial[NBLK];
__device__ unsigned int g_count = 0;

struct Smem {
    __nv_bfloat16 Ahi[128 * AP];            // 67584 B  rows: wg*64 + v*16 + p
    __nv_bfloat16 Alo[128 * AP];            // 67584 B
    __nv_bfloat16 Wb[2][2][2][BTILE];       // 65536 B  [wg][buf][hi/lo], swizzled tiles
    float bias_s[2][HDIM];                  // per-WG bias copy
    float W1s[3][HDIM];
    float W4Ts[6][HDIM];
    float OUT[4][32][6];
    float coords[32][3];
    float b4s[6];
    float warp_s[16];
    int   done;
};

// ---------------- asm helpers (baseline sm_80+ PTX only) ----------------
__device__ __forceinline__ uint32_t smem_u32(const void* p) {
    uint32_t a;
    asm("{ .reg .u64 t; cvta.to.shared.u64 t, %1; cvt.u32.u64 %0, t; }" : "=r"(a) : "l"(p));
    return a;
}
#define CP_ASYNC16(dst, src) \
    asm volatile("cp.async.cg.shared.global [%0], [%1], 16;" :: "r"(dst), "l"(src))
#define CP_COMMIT()  asm volatile("cp.async.commit_group;" ::: "memory")
#define CP_WAIT0()   asm volatile("cp.async.wait_group 0;" ::: "memory")

#define LDSM4(r0, r1, r2, r3, addr) \
    asm volatile("ldmatrix.sync.aligned.m8n8.x4.shared.b16 {%0,%1,%2,%3}, [%4];" \
                 : "=r"(r0), "=r"(r1), "=r"(r2), "=r"(r3) : "r"(addr))

#define MMA16816(d, a, b0, b1) \
    asm volatile("mma.sync.aligned.m16n8k16.row.col.f32.bf16.bf16.f32 " \
                 "{%0,%1,%2,%3}, {%4,%5,%6,%7}, {%8,%9}, {%0,%1,%2,%3};" \
                 : "+f"((d)[0]), "+f"((d)[1]), "+f"((d)[2]), "+f"((d)[3]) \
                 : "r"((a)[0]), "r"((a)[1]), "r"((a)[2]), "r"((a)[3]), \
                   "r"(b0), "r"(b1))

// warp-group barrier: 256 threads, id 1+wg
#define BARWG(wg) asm volatile("bar.sync %0, 256;" :: "r"(1 + (wg)) : "memory")

__device__ __forceinline__ void split_bf16(float v, __nv_bfloat16& hi, __nv_bfloat16& lo) {
    hi = __float2bfloat16(v);
    lo = __float2bfloat16(v - __bfloat162float(hi));
}
__device__ __forceinline__ void split2_store(__nv_bfloat16* hi_p, __nv_bfloat16* lo_p,
                                             float v0, float v1) {
    __nv_bfloat162 h2 = __floats2bfloat162_rn(v0, v1);
    __nv_bfloat162 l2 = __floats2bfloat162_rn(v0 - __bfloat162float(h2.x),
                                              v1 - __bfloat162float(h2.y));
    *(__nv_bfloat162*)hi_p = h2;
    *(__nv_bfloat162*)lo_p = l2;
}

// B tile swizzle: logical (n, kbyte in {0,16}) -> byte offset in 8192B tile.
// 16B slots; 8 consecutive n rows at fixed kbyte hit 8 distinct 128B-slots.
__device__ __forceinline__ uint32_t btile_off(uint32_t n, uint32_t kbyte) {
    return ((n >> 2) << 7) + ((n & 3) << 5) + (kbyte ^ (((n >> 2) & 1) << 4));
}

// ---------------- prep: W2/W3 fp32 [k][n] -> g_Wt[L][hi/lo][n][k] bf16 ----------------
__global__ void prep_kernel(const float* __restrict__ W2, const float* __restrict__ W3) {
    __shared__ float t[32][33];
    const float* W = blockIdx.z ? W3 : W2;
    const int tx = threadIdx.x, ty = threadIdx.y;
    const int bx = blockIdx.x, by = blockIdx.y, L = blockIdx.z;
    #pragma unroll
    for (int i = 0; i < 4; i++) {
        int lk = ty + i * 8;
        t[lk][tx] = W[(by * 32 + lk) * HDIM + bx * 32 + tx];
    }
    __syncthreads();
    #pragma unroll
    for (int i = 0; i < 4; i++) {
        int ln = ty + i * 8;
        int n = bx * 32 + ln;
        int k = by * 32 + tx;
        float w = t[tx][ln];
        __nv_bfloat16 hi, lo;
        split_bf16(w, hi, lo);
        g_Wt[L][0][n * HDIM + k] = hi;
        g_Wt[L][1][n * HDIM + k] = lo;
    }
}

// ---------------- main fused kernel ----------------
__global__ void __launch_bounds__(NTH, 1)
mhd_kernel(const float* __restrict__ coords,
           const float* __restrict__ W1, const float* __restrict__ b1,
           const float* __restrict__ b2, const float* __restrict__ b3,
           const float* __restrict__ W4, const float* __restrict__ b4,
           const float* __restrict__ wts, float* __restrict__ out) {
    extern __shared__ char raw[];
    Smem* s = (Smem*)raw;
    const int tid = threadIdx.x, lane = tid & 31;
    const int wg = tid >> 8;               // warp-group 0/1
    const int wgt = tid & 255;             // thread within WG
    const int wwid = wgt >> 5;             // warp within WG 0-7
    const int wm = wwid >> 2, wn = wwid & 3;   // 2x4 warp grid (M=64, N=256)
    const int gid = lane >> 2, tig = lane & 3; // mma fragment coords

    const uint32_t ahi_b = smem_u32(s->Ahi);
    const uint32_t alo_b = smem_u32(s->Alo);
    const uint32_t wb_b  = smem_u32(s->Wb);
    float* sdwg = (float*)&s->Wb[wg][0][0][0];   // epilogue alias: sd[16][AP]

    // ---- stage constants ----
    for (int i = tid; i < 3 * HDIM; i += NTH) ((float*)s->W1s)[i] = W1[i];
    for (int i = tid; i < 6 * HDIM; i += NTH) {
        int k = i / 6, j = i % 6;
        s->W4Ts[j][k] = W4[i];
    }
    if (tid < PTS * 3) ((float*)s->coords)[tid] = coords[blockIdx.x * PTS * 3 + tid];
    if (tid < 6) s->b4s[tid] = b4[tid];
    __syncthreads();

    // ---- layer 1: 3 -> 256, seed A rows [wg][v][p] ----
    #pragma unroll
    for (int i = 0; i < 8; i++) {
        int idx = tid + i * NTH;                 // 0..4095
        int pg = idx >> 7, n = (idx & 127) * 2;  // global point, col pair
        int rb = (pg >> 4) * 64 + (pg & 15);     // base row (v=0)
        float w00 = s->W1s[0][n], w01 = s->W1s[0][n + 1];
        float w10 = s->W1s[1][n], w11 = s->W1s[1][n + 1];
        float w20 = s->W1s[2][n], w21 = s->W1s[2][n + 1];
        float c0 = s->coords[pg][0], c1 = s->coords[pg][1], c2 = s->coords[pg][2];
        float z0 = fmaf(c2, w20, fmaf(c1, w10, fmaf(c0, w00, b1[n])));
        float z1 = fmaf(c2, w21, fmaf(c1, w11, fmaf(c0, w01, b1[n + 1])));
        float h0 = tanhf(z0), h1 = tanhf(z1);
        float sd0 = 1.f - h0 * h0, sd1 = 1.f - h1 * h1;
        split2_store(&s->Ahi[rb * AP + n],        &s->Alo[rb * AP + n],        h0, h1);
        split2_store(&s->Ahi[(rb + 16) * AP + n], &s->Alo[(rb + 16) * AP + n], sd0 * w00, sd1 * w01);
        split2_store(&s->Ahi[(rb + 32) * AP + n], &s->Alo[(rb + 32) * AP + n], sd0 * w10, sd1 * w11);
        split2_store(&s->Ahi[(rb + 48) * AP + n], &s->Alo[(rb + 48) * AP + n], sd0 * w20, sd1 * w21);
    }
    __syncthreads();

    // per-lane precomputed addresses
    const uint32_t a_row = (uint32_t)(wg * 64 + wm * 32 + (lane & 15));
    const uint32_t a_colsel = (uint32_t)((lane >> 4) << 3);
    const uint32_t b_ln = (uint32_t)(wn * 64 + (lane & 7) + ((lane >> 4) << 3));
    const uint32_t b_kb16 = (uint32_t)(((lane >> 3) & 1) << 4);
    const uint32_t b_const = btile_off(b_ln, b_kb16);  // np advances by +512B

    // ---- layers 2 & 3 : per-WG pipelined HMMA, 3-sweep split-bf16 ----
    const float* biases[2] = {b2, b3};
    for (int L = 0; L < 2; L++) {
        s->bias_s[wg][wgt] = biases[L][wgt];

        auto load_chunk = [&](int buf, int kb) {
            #pragma unroll
            for (int i = 0; i < 4; i++) {
                int id = wgt + i * 256;          // 0..1023
                int h = id >> 9;                 // hi/lo
                int r = id & 511;
                int n = r >> 1, s8h = r & 1;
                const __nv_bfloat16* src = &g_Wt[L][h][n * HDIM + kb + s8h * 8];
                uint32_t dst = wb_b + (uint32_t)(((wg * 2 + buf) * 2 + h) * (BTILE * 2))
                             + btile_off((uint32_t)n, (uint32_t)(s8h * 16));
                CP_ASYNC16(dst, (const void*)src);
            }
            CP_COMMIT();
        };

        load_chunk(0, 0);

        float acc[2][8][4];
        #pragma unroll
        for (int mt = 0; mt < 2; mt++)
            #pragma unroll
            for (int nt = 0; nt < 8; nt++)
                #pragma unroll
                for (int e = 0; e < 4; e++) acc[mt][nt][e] = 0.f;

        for (int c = 0; c < NCH; c++) {
            CP_WAIT0();
            BARWG(wg);
            if (c + 1 < NCH) load_chunk((c + 1) & 1, (c + 1) * KCH);
            const int buf = c & 1;
            const uint32_t whi = wb_b + (uint32_t)(((wg * 2 + buf) * 2 + 0) * (BTILE * 2));
            const uint32_t wlo = whi + (uint32_t)(BTILE * 2);

            const uint32_t a_off = (a_row * AP + (uint32_t)(c * KCH) + a_colsel) * 2u;
            uint32_t ah[2][4], al[2][4];
            LDSM4(ah[0][0], ah[0][1], ah[0][2], ah[0][3], ahi_b + a_off);
            LDSM4(ah[1][0], ah[1][1], ah[1][2], ah[1][3], ahi_b + a_off + 16u * AP * 2u);
            LDSM4(al[0][0], al[0][1], al[0][2], al[0][3], alo_b + a_off);
            LDSM4(al[1][0], al[1][1], al[1][2], al[1][3], alo_b + a_off + 16u * AP * 2u);

            #pragma unroll
            for (int nh = 0; nh < 2; nh++) {
                uint32_t bh[2][4];
                LDSM4(bh[0][0], bh[0][1], bh[0][2], bh[0][3],
                      whi + b_const + (uint32_t)((nh * 2 + 0) * 512));
                LDSM4(bh[1][0], bh[1][1], bh[1][2], bh[1][3],
                      whi + b_const + (uint32_t)((nh * 2 + 1) * 512));
                #pragma unroll
                for (int mt = 0; mt < 2; mt++)
                    #pragma unroll
                    for (int ntl = 0; ntl < 4; ntl++)
                        MMA16816(acc[mt][nh * 4 + ntl], ah[mt],
                                 bh[ntl >> 1][(ntl & 1) * 2], bh[ntl >> 1][(ntl & 1) * 2 + 1]);
                #pragma unroll
                for (int mt = 0; mt < 2; mt++)
                    #pragma unroll
                    for (int ntl = 0; ntl < 4; ntl++)
                        MMA16816(acc[mt][nh * 4 + ntl], al[mt],
                                 bh[ntl >> 1][(ntl & 1) * 2], bh[ntl >> 1][(ntl & 1) * 2 + 1]);
                uint32_t bl[2][4];
                LDSM4(bl[0][0], bl[0][1], bl[0][2], bl[0][3],
                      wlo + b_const + (uint32_t)((nh * 2 + 0) * 512));
                LDSM4(bl[1][0], bl[1][1], bl[1][2], bl[1][3],
                      wlo + b_const + (uint32_t)((nh * 2 + 1) * 512));
                #pragma unroll
                for (int mt = 0; mt < 2; mt++)
                    #pragma unroll
                    for (int ntl = 0; ntl < 4; ntl++)
                        MMA16816(acc[mt][nh * 4 + ntl], ah[mt],
                                 bl[ntl >> 1][(ntl & 1) * 2], bl[ntl >> 1][(ntl & 1) * 2 + 1]);
            }
        }
        BARWG(wg);   // all WG warps done with W tiles -> sd alias is safe

        // ---- epilogue (per WG): primal tanh + sd publish, then tangent scale ----
        if (wm == 0) {
            // mt = 0 tile: rows = v0 (p = gid + eh*8)
            #pragma unroll
            for (int nt = 0; nt < 8; nt++) {
                int nb = wn * 64 + nt * 8 + 2 * tig;
                #pragma unroll
                for (int eh = 0; eh < 2; eh++) {
                    int p = gid + eh * 8;
                    int r = wg * 64 + p;
                    float z0 = acc[0][nt][eh * 2]     + s->bias_s[wg][nb];
                    float z1 = acc[0][nt][eh * 2 + 1] + s->bias_s[wg][nb + 1];
                    float h0 = tanhf(z0), h1 = tanhf(z1);
                    split2_store(&s->Ahi[r * AP + nb], &s->Alo[r * AP + nb], h0, h1);
                    sdwg[p * AP + nb]     = 1.f - h0 * h0;
                    sdwg[p * AP + nb + 1] = 1.f - h1 * h1;
                }
            }
        }
        BARWG(wg);
        #pragma unroll
        for (int mt = 0; mt < 2; mt++) {
            if (wm == 0 && mt == 0) continue;      // primal already done
            #pragma unroll
            for (int nt = 0; nt < 8; nt++) {
                int nb = wn * 64 + nt * 8 + 2 * tig;
                #pragma unroll
                for (int eh = 0; eh < 2; eh++) {
                    int p = gid + eh * 8;
                    int r = wg * 64 + wm * 32 + mt * 16 + p;
                    float v0 = acc[mt][nt][eh * 2]     * sdwg[p * AP + nb];
                    float v1 = acc[mt][nt][eh * 2 + 1] * sdwg[p * AP + nb + 1];
                    split2_store(&s->Ahi[r * AP + nb], &s->Alo[r * AP + nb], v0, v1);
                }
            }
        }
        BARWG(wg);   // sd reads done; next layer may overwrite Wb
    }
    __syncthreads();

    // ---- layer 4: 256 -> 6, k-split over 4 threads per row ----
    {
        int row = tid >> 2;                    // A row 0..127 = [wg][v][p]
        int ks = tid & 3;
        float acc4[6] = {0.f, 0.f, 0.f, 0.f, 0.f, 0.f};
        #pragma unroll 8
        for (int k = ks * 64; k < ks * 64 + 64; k++) {
            float a = __bfloat162float(s->Ahi[row * AP + k]) +
                      __bfloat162float(s->Alo[row * AP + k]);
            #pragma unroll
            for (int j = 0; j < 6; j++)
                acc4[j] = fmaf(a, s->W4Ts[j][k], acc4[j]);
        }
        #pragma unroll
        for (int j = 0; j < 6; j++) {
            acc4[j] += __shfl_down_sync(0xffffffffu, acc4[j], 2, 4);
            acc4[j] += __shfl_down_sync(0xffffffffu, acc4[j], 1, 4);
        }
        if (ks == 0) {
            int v = (row >> 4) & 3;
            int point = (row >> 6) * 16 + (row & 15);
            #pragma unroll
            for (int j = 0; j < 6; j++)
                s->OUT[v][point][j] = acc4[j] + ((v == 0) ? s->b4s[j] : 0.f);
        }
    }
    __syncthreads();

    // ---- residuals + block reduction (warp 0) ----
    if (tid < 32) {
        const int m = lane;
        const float* P  = s->OUT[0][m];
        const float* Jx = s->OUT[1][m];
        const float* Jy = s->OUT[2][m];
        const float* Jt = s->OUT[3][m];
        const float rho = P[0], vx = P[1], vy = P[2], Bx = P[3], By = P[4], Pp = P[5];
        const float ig = 1.f / (GAMMA_F - 1.f);

        const float dt_rho = Jt[0], dt_Bx = Jt[3], dt_By = Jt[4];
        const float dt_rhovx = dt_rho * vx + rho * Jt[1];
        const float dt_rhovy = dt_rho * vy + rho * Jt[2];

        #define DE(Jc) ((Jc)[5] * ig + 0.5f * (Jc)[0] * (vx * vx + vy * vy) \
                        + rho * (vx * (Jc)[1] + vy * (Jc)[2]) + Bx * (Jc)[3] + By * (Jc)[4])
        #define DG(Jc) ((Jc)[1] * By + vx * (Jc)[4] - (Jc)[2] * Bx - vy * (Jc)[3])
        #define DD(Jc) ((Jc)[3] * vx + Bx * (Jc)[1] + (Jc)[4] * vy + By * (Jc)[2])

        const float dE_dx = DE(Jx), dE_dy = DE(Jy), dE_dt = DE(Jt);
        const float div_v = Jx[1] + Jy[2];
        const float div_B = Jx[3] + Jy[4];
        const float continuity = dt_rho + rho * div_v;
        const float dPm_dx = Jx[5] + Bx * Jx[3] + By * Jx[4];
        const float dPm_dy = Jy[5] + Bx * Jy[3] + By * Jy[4];
        const float momentum_x = dt_rhovx + dPm_dx - (Bx * Jx[3] + By * Jy[3]);
        const float momentum_y = dt_rhovy + dPm_dy - (Bx * Jx[4] + By * Jy[4]);
        const float induction_x = dt_Bx + DG(Jy);
        const float induction_y = dt_By - DG(Jx);
        const float Ee = Pp * ig + 0.5f * rho * (vx * vx + vy * vy) + 0.5f * (Bx * Bx + By * By);
        const float S  = Ee + Pp + 0.5f * (Bx * Bx + By * By);
        const float dS_dx = dE_dx + Jx[5] + Bx * Jx[3] + By * Jx[4];
        const float dS_dy = dE_dy + Jy[5] + Bx * Jy[3] + By * Jy[4];
        const float D = Bx * vx + By * vy;
        const float dFx_dx = dS_dx * vx + S * Jx[1] - DD(Jx) * Bx - D * Jx[3];
        const float dFy_dy = dS_dy * vy + S * Jy[2] - DD(Jy) * By - D * Jy[4];
        const float energy = dE_dt + dFx_dx + dFy_dy;

        float Sm = wts[0] * continuity * continuity
                 + wts[1] * momentum_x * momentum_x
                 + wts[2] * momentum_y * momentum_y
                 + wts[3] * induction_x * induction_x
                 + wts[4] * induction_y * induction_y
                 + wts[5] * energy * energy
                 + wts[6] * div_B * div_B;

        #pragma unroll
        for (int off = 16; off; off >>= 1)
            Sm += __shfl_down_sync(0xffffffffu, Sm, off);
        if (m == 0) g_partial[blockIdx.x] = Sm;
    }

    // ---- last-block final reduction (deterministic) ----
    if (tid == 0) {
        __threadfence();
        unsigned int ticket = atomicAdd(&g_count, 1u);
        s->done = (ticket == NBLK - 1) ? 1 : 0;
    }
    __syncthreads();
    if (s->done) {
        __threadfence();
        float sum = 0.f;
        for (int i = tid; i < NBLK; i += NTH) sum += g_partial[i];
        #pragma unroll
        for (int off = 16; off; off >>= 1) sum += __shfl_down_sync(0xffffffffu, sum, off);
        if (lane == 0) s->warp_s[tid >> 5] = sum;
        __syncthreads();
        if (tid < 32) {
            sum = (lane < 16) ? s->warp_s[lane] : 0.f;
            #pragma unroll
            for (int off = 8; off; off >>= 1) sum += __shfl_down_sync(0xffffffffu, sum, off);
            if (lane == 0) {
                out[0] = sum / (float)NPTS;
                g_count = 0;
            }
        }
    }
}

extern "C" void kernel_launch(void* const* d_in, const int* in_sizes, int n_in,
                              void* d_out, int out_size) {
    const float* coords = (const float*)d_in[0];
    const float* W1     = (const float*)d_in[1];
    const float* b1     = (const float*)d_in[2];
    const float* W2     = (const float*)d_in[3];
    const float* b2     = (const float*)d_in[4];
    const float* W3     = (const float*)d_in[5];
    const float* b3     = (const float*)d_in[6];
    const float* W4     = (const float*)d_in[7];
    const float* b4     = (const float*)d_in[8];
    const float* wts    = (const float*)d_in[9];

    prep_kernel<<<dim3(8, 8, 2), dim3(32, 8)>>>(W2, W3);

    const size_t smem_bytes = sizeof(Smem);
    cudaFuncSetAttribute(mhd_kernel, cudaFuncAttributeMaxDynamicSharedMemorySize,
                         (int)smem_bytes);
    mhd_kernel<<<NBLK, NTH, smem_bytes>>>(coords, W1, b1, b2, b3, W4, b4, wts,
                                          (float*)d_out);
}

// round 11
// speedup vs baseline: 2.3406x; 2.3406x over previous
#include <cuda_runtime.h>
#include <cuda_fp16.h>
#include <math.h>
#include <stdint.h>

#define NPTS     131072
#define HDIM     256
#define PTS      16              // points per CTA
#define NTH      256             // 8 warps, 2x4 grid
#define NBLK     (NPTS / PTS)    // 8192
#define AP       264             // A smem pitch (halfs): 528B, conflict-free ldmatrix
#define KCH      32              // K chunk
#define NCH      (HDIM / KCH)    // 8
#define BTILEB   16384           // bytes per B tile (256 n x 32 k x 2B)
#define GAMMA_F  (5.0f / 3.0f)

__device__ __align__(16) __half g_Wt[2][2][HDIM * HDIM];  // [layer][hi/lo][n*256+k]
__device__ float g_partial[NBLK];
__device__ unsigned int g_count = 0;

struct __align__(16) Smem {
    __half A[64 * AP];              // 33792 B   rows: v*16 + p
    __half Wb[2][2][HDIM * KCH];    // 65536 B   [buf][hi/lo] swizzled; aliased as sd in epilogue
    float bias_s[HDIM];
    float W1s[3][HDIM];
    float W4Ts[6][HDIM];
    float OUT[4][PTS][6];
    float coords[PTS][3];
    float b4s[6];
    float warp_s[8];
    int   done;
};

// ---------------- asm helpers (baseline sm_80+ PTX only) ----------------
__device__ __forceinline__ uint32_t smem_u32(const void* p) {
    uint32_t a;
    asm("{ .reg .u64 t; cvta.to.shared.u64 t, %1; cvt.u32.u64 %0, t; }" : "=r"(a) : "l"(p));
    return a;
}
#define CP_ASYNC16(dst, src) \
    asm volatile("cp.async.cg.shared.global [%0], [%1], 16;" :: "r"(dst), "l"(src))
#define CP_COMMIT()  asm volatile("cp.async.commit_group;" ::: "memory")
#define CP_WAIT0()   asm volatile("cp.async.wait_group 0;" ::: "memory")

#define LDSM4(r0, r1, r2, r3, addr) \
    asm volatile("ldmatrix.sync.aligned.m8n8.x4.shared.b16 {%0,%1,%2,%3}, [%4];" \
                 : "=r"(r0), "=r"(r1), "=r"(r2), "=r"(r3) : "r"(addr))

#define MMAF16(d, a, b0, b1) \
    asm volatile("mma.sync.aligned.m16n8k16.row.col.f32.f16.f16.f32 " \
                 "{%0,%1,%2,%3}, {%4,%5,%6,%7}, {%8,%9}, {%0,%1,%2,%3};" \
                 : "+f"((d)[0]), "+f"((d)[1]), "+f"((d)[2]), "+f"((d)[3]) \
                 : "r"((a)[0]), "r"((a)[1]), "r"((a)[2]), "r"((a)[3]), \
                   "r"(b0), "r"(b1))

// B tile swizzle: (n, kbyte in {0,16,32,48}) -> byte offset in 16KB tile.
// slot = 4n + (kb>>4 ^ ((n>>1)&3)) mod 8 covers 8 distinct 16B banks for any
// 8 consecutive n at fixed kb (ldmatrix), and for cp.async store groups.
__device__ __forceinline__ uint32_t btile_off(uint32_t n, uint32_t kbyte) {
    return n * 64u + (kbyte ^ (((n >> 1) & 3u) << 4));
}

__device__ __forceinline__ void splitw(float v, __half& hi, __half& lo) {
    hi = __float2half_rn(v);
    lo = __float2half_rn(v - __half2float(hi));
}

// ---------------- prep: W2/W3 fp32 [k][n] -> g_Wt[L][hi/lo][n][k] fp16 ----------------
__global__ void prep_kernel(const float* __restrict__ W2, const float* __restrict__ W3) {
    __shared__ float t[32][33];
    const float* W = blockIdx.z ? W3 : W2;
    const int tx = threadIdx.x, ty = threadIdx.y;
    const int bx = blockIdx.x, by = blockIdx.y, L = blockIdx.z;
    #pragma unroll
    for (int i = 0; i < 4; i++) {
        int lk = ty + i * 8;
        t[lk][tx] = W[(by * 32 + lk) * HDIM + bx * 32 + tx];
    }
    __syncthreads();
    #pragma unroll
    for (int i = 0; i < 4; i++) {
        int ln = ty + i * 8;
        int n = bx * 32 + ln;
        int k = by * 32 + tx;
        __half hi, lo;
        splitw(t[tx][ln], hi, lo);
        g_Wt[L][0][n * HDIM + k] = hi;
        g_Wt[L][1][n * HDIM + k] = lo;
    }
}

// ---------------- main fused kernel ----------------
__global__ void __launch_bounds__(NTH, 2)
mhd_kernel(const float* __restrict__ coords,
           const float* __restrict__ W1, const float* __restrict__ b1,
           const float* __restrict__ b2, const float* __restrict__ b3,
           const float* __restrict__ W4, const float* __restrict__ b4,
           const float* __restrict__ wts, float* __restrict__ out) {
    extern __shared__ char raw[];
    Smem* s = (Smem*)raw;
    const int tid = threadIdx.x, wid = tid >> 5, lane = tid & 31;
    const int wm = wid >> 2, wn = wid & 3;         // 2x4 warp grid (M=64, N=256)
    const int gid = lane >> 2, tig = lane & 3;     // fragment coords

    const uint32_t a_b  = smem_u32(s->A);
    const uint32_t wb_b = smem_u32(s->Wb);
    __half* sdbuf = (__half*)s->Wb;                // epilogue alias: sd[p*AP+n]

    // ---- stage constants ----
    for (int i = tid; i < 3 * HDIM; i += NTH) ((float*)s->W1s)[i] = W1[i];
    for (int i = tid; i < 6 * HDIM; i += NTH) {
        int k = i / 6, j = i % 6;
        s->W4Ts[j][k] = W4[i];
    }
    if (tid < PTS * 3) ((float*)s->coords)[tid] = coords[blockIdx.x * PTS * 3 + tid];
    if (tid < 6) s->b4s[tid] = b4[tid];
    __syncthreads();

    // ---- layer 1: 3 -> 256, seed A rows v*16+p ----
    #pragma unroll
    for (int i = 0; i < 8; i++) {
        int idx = tid + i * NTH;                 // 0..2047
        int p = idx >> 7, n = (idx & 127) * 2;
        float w00 = s->W1s[0][n], w01 = s->W1s[0][n + 1];
        float w10 = s->W1s[1][n], w11 = s->W1s[1][n + 1];
        float w20 = s->W1s[2][n], w21 = s->W1s[2][n + 1];
        float c0 = s->coords[p][0], c1 = s->coords[p][1], c2 = s->coords[p][2];
        float z0 = fmaf(c2, w20, fmaf(c1, w10, fmaf(c0, w00, b1[n])));
        float z1 = fmaf(c2, w21, fmaf(c1, w11, fmaf(c0, w01, b1[n + 1])));
        float h0 = tanhf(z0), h1 = tanhf(z1);
        float sd0 = 1.f - h0 * h0, sd1 = 1.f - h1 * h1;
        *(__half2*)&s->A[p * AP + n]        = __floats2half2_rn(h0, h1);
        *(__half2*)&s->A[(16 + p) * AP + n] = __floats2half2_rn(sd0 * w00, sd1 * w01);
        *(__half2*)&s->A[(32 + p) * AP + n] = __floats2half2_rn(sd0 * w10, sd1 * w11);
        *(__half2*)&s->A[(48 + p) * AP + n] = __floats2half2_rn(sd0 * w20, sd1 * w21);
    }
    __syncthreads();

    // per-lane ldmatrix address components
    const uint32_t a_row = (uint32_t)(wm * 32 + (lane & 15));
    const uint32_t a_colsel = (uint32_t)((lane >> 4) << 3);
    const uint32_t b_ln = (uint32_t)(wn * 64 + (lane & 7) + ((lane >> 4) << 3));
    const uint32_t b_ksel16 = (uint32_t)(((lane >> 3) & 1) << 4);
    const uint32_t b_xor = ((b_ln >> 1) & 3u) << 4;
    const uint32_t b_base = b_ln * 64u;            // np step: +1024B (xor invariant)

    // ---- layers 2 & 3: pipelined HMMA, 2-sweep (A fp16 x [Whi + Wlo]) ----
    const float* biases[2] = {b2, b3};
    for (int L = 0; L < 2; L++) {
        s->bias_s[tid] = biases[L][tid];

        auto load_chunk = [&](int buf, int kb) {
            #pragma unroll
            for (int i = 0; i < 8; i++) {
                int id = tid + i * NTH;            // 0..2047
                int h = id >> 10;                  // hi/lo
                int r = id & 1023;
                int n = r >> 2, ks = r & 3;
                const __half* src = &g_Wt[L][h][n * HDIM + kb + ks * 8];
                uint32_t dst = wb_b + (uint32_t)((buf * 2 + h) * BTILEB)
                             + btile_off((uint32_t)n, (uint32_t)(ks * 16));
                CP_ASYNC16(dst, (const void*)src);
            }
            CP_COMMIT();
        };

        load_chunk(0, 0);

        float acc[2][8][4];
        #pragma unroll
        for (int mt = 0; mt < 2; mt++)
            #pragma unroll
            for (int nt = 0; nt < 8; nt++)
                #pragma unroll
                for (int e = 0; e < 4; e++) acc[mt][nt][e] = 0.f;

        for (int c = 0; c < NCH; c++) {
            CP_WAIT0();
            __syncthreads();
            if (c + 1 < NCH) load_chunk((c + 1) & 1, (c + 1) * KCH);
            const int buf = c & 1;
            const uint32_t whi = wb_b + (uint32_t)(buf * 2 * BTILEB);
            const uint32_t wlo = whi + (uint32_t)BTILEB;

            #pragma unroll
            for (int kk2 = 0; kk2 < 2; kk2++) {
                const uint32_t a_off = (a_row * AP + (uint32_t)(c * KCH + kk2 * 16) + a_colsel) * 2u;
                uint32_t ah[2][4];
                LDSM4(ah[0][0], ah[0][1], ah[0][2], ah[0][3], a_b + a_off);
                LDSM4(ah[1][0], ah[1][1], ah[1][2], ah[1][3], a_b + a_off + 16u * AP * 2u);

                const uint32_t bco = b_base + (((uint32_t)(kk2 * 32) + b_ksel16) ^ b_xor);
                #pragma unroll
                for (int nh = 0; nh < 2; nh++) {
                    uint32_t bh[2][4];
                    LDSM4(bh[0][0], bh[0][1], bh[0][2], bh[0][3],
                          whi + bco + (uint32_t)((nh * 2 + 0) * 1024));
                    LDSM4(bh[1][0], bh[1][1], bh[1][2], bh[1][3],
                          whi + bco + (uint32_t)((nh * 2 + 1) * 1024));
                    #pragma unroll
                    for (int mt = 0; mt < 2; mt++)
                        #pragma unroll
                        for (int ntl = 0; ntl < 4; ntl++)
                            MMAF16(acc[mt][nh * 4 + ntl], ah[mt],
                                   bh[ntl >> 1][(ntl & 1) * 2], bh[ntl >> 1][(ntl & 1) * 2 + 1]);
                    uint32_t bl[2][4];
                    LDSM4(bl[0][0], bl[0][1], bl[0][2], bl[0][3],
                          wlo + bco + (uint32_t)((nh * 2 + 0) * 1024));
                    LDSM4(bl[1][0], bl[1][1], bl[1][2], bl[1][3],
                          wlo + bco + (uint32_t)((nh * 2 + 1) * 1024));
                    #pragma unroll
                    for (int mt = 0; mt < 2; mt++)
                        #pragma unroll
                        for (int ntl = 0; ntl < 4; ntl++)
                            MMAF16(acc[mt][nh * 4 + ntl], ah[mt],
                                   bl[ntl >> 1][(ntl & 1) * 2], bl[ntl >> 1][(ntl & 1) * 2 + 1]);
                }
            }
        }
        __syncthreads();   // MMAs done; Wb free -> sd alias

        // ---- epilogue: primal tile (wm=0, mt=0) tanh + sd; others scale ----
        if (wm == 0) {
            #pragma unroll
            for (int nt = 0; nt < 8; nt++) {
                int nb = wn * 64 + nt * 8 + 2 * tig;
                #pragma unroll
                for (int eh = 0; eh < 2; eh++) {
                    int p = gid + eh * 8;
                    float z0 = acc[0][nt][eh * 2]     + s->bias_s[nb];
                    float z1 = acc[0][nt][eh * 2 + 1] + s->bias_s[nb + 1];
                    float h0 = tanhf(z0), h1 = tanhf(z1);
                    *(__half2*)&s->A[p * AP + nb] = __floats2half2_rn(h0, h1);
                    *(__half2*)&sdbuf[p * AP + nb] =
                        __floats2half2_rn(1.f - h0 * h0, 1.f - h1 * h1);
                }
            }
        }
        __syncthreads();
        #pragma unroll
        for (int mt = 0; mt < 2; mt++) {
            if (wm == 0 && mt == 0) continue;        // primal already written
            #pragma unroll
            for (int nt = 0; nt < 8; nt++) {
                int nb = wn * 64 + nt * 8 + 2 * tig;
                #pragma unroll
                for (int eh = 0; eh < 2; eh++) {
                    int p = gid + eh * 8;
                    int r = wm * 32 + mt * 16 + p;
                    __half2 sd2 = *(__half2*)&sdbuf[p * AP + nb];
                    float v0 = acc[mt][nt][eh * 2]     * __half2float(sd2.x);
                    float v1 = acc[mt][nt][eh * 2 + 1] * __half2float(sd2.y);
                    *(__half2*)&s->A[r * AP + nb] = __floats2half2_rn(v0, v1);
                }
            }
        }
        __syncthreads();   // sd reads done; next layer may overwrite Wb
    }

    // ---- layer 4: 256 -> 6, k-split over 4 threads per row ----
    {
        int row = tid >> 2;                        // 0..63 = v*16+p
        int ks = tid & 3;
        float acc4[6] = {0.f, 0.f, 0.f, 0.f, 0.f, 0.f};
        #pragma unroll 8
        for (int k = ks * 64; k < ks * 64 + 64; k++) {
            float a = __half2float(s->A[row * AP + k]);
            #pragma unroll
            for (int j = 0; j < 6; j++)
                acc4[j] = fmaf(a, s->W4Ts[j][k], acc4[j]);
        }
        #pragma unroll
        for (int j = 0; j < 6; j++) {
            acc4[j] += __shfl_down_sync(0xffffffffu, acc4[j], 2, 4);
            acc4[j] += __shfl_down_sync(0xffffffffu, acc4[j], 1, 4);
        }
        if (ks == 0) {
            int v = row >> 4, p = row & 15;
            #pragma unroll
            for (int j = 0; j < 6; j++)
                s->OUT[v][p][j] = acc4[j] + ((v == 0) ? s->b4s[j] : 0.f);
        }
    }
    __syncthreads();

    // ---- residuals + reduction over the CTA's 16 points ----
    if (tid < PTS) {
        const int m = tid;
        const float* P  = s->OUT[0][m];
        const float* Jx = s->OUT[1][m];
        const float* Jy = s->OUT[2][m];
        const float* Jt = s->OUT[3][m];
        const float rho = P[0], vx = P[1], vy = P[2], Bx = P[3], By = P[4], Pp = P[5];
        const float ig = 1.f / (GAMMA_F - 1.f);

        const float dt_rho = Jt[0], dt_Bx = Jt[3], dt_By = Jt[4];
        const float dt_rhovx = dt_rho * vx + rho * Jt[1];
        const float dt_rhovy = dt_rho * vy + rho * Jt[2];

        #define DE(Jc) ((Jc)[5] * ig + 0.5f * (Jc)[0] * (vx * vx + vy * vy) \
                        + rho * (vx * (Jc)[1] + vy * (Jc)[2]) + Bx * (Jc)[3] + By * (Jc)[4])
        #define DG(Jc) ((Jc)[1] * By + vx * (Jc)[4] - (Jc)[2] * Bx - vy * (Jc)[3])
        #define DD(Jc) ((Jc)[3] * vx + Bx * (Jc)[1] + (Jc)[4] * vy + By * (Jc)[2])

        const float dE_dx = DE(Jx), dE_dy = DE(Jy), dE_dt = DE(Jt);
        const float div_v = Jx[1] + Jy[2];
        const float div_B = Jx[3] + Jy[4];
        const float continuity = dt_rho + rho * div_v;
        const float dPm_dx = Jx[5] + Bx * Jx[3] + By * Jx[4];
        const float dPm_dy = Jy[5] + Bx * Jy[3] + By * Jy[4];
        const float momentum_x = dt_rhovx + dPm_dx - (Bx * Jx[3] + By * Jy[3]);
        const float momentum_y = dt_rhovy + dPm_dy - (Bx * Jx[4] + By * Jy[4]);
        const float induction_x = dt_Bx + DG(Jy);
        const float induction_y = dt_By - DG(Jx);
        const float Ee = Pp * ig + 0.5f * rho * (vx * vx + vy * vy) + 0.5f * (Bx * Bx + By * By);
        const float S  = Ee + Pp + 0.5f * (Bx * Bx + By * By);
        const float dS_dx = dE_dx + Jx[5] + Bx * Jx[3] + By * Jx[4];
        const float dS_dy = dE_dy + Jy[5] + Bx * Jy[3] + By * Jy[4];
        const float D = Bx * vx + By * vy;
        const float dFx_dx = dS_dx * vx + S * Jx[1] - DD(Jx) * Bx - D * Jx[3];
        const float dFy_dy = dS_dy * vy + S * Jy[2] - DD(Jy) * By - D * Jy[4];
        const float energy = dE_dt + dFx_dx + dFy_dy;

        float Sm = wts[0] * continuity * continuity
                 + wts[1] * momentum_x * momentum_x
                 + wts[2] * momentum_y * momentum_y
                 + wts[3] * induction_x * induction_x
                 + wts[4] * induction_y * induction_y
                 + wts[5] * energy * energy
                 + wts[6] * div_B * div_B;

        #pragma unroll
        for (int off = 8; off; off >>= 1)
            Sm += __shfl_down_sync(0x0000ffffu, Sm, off, 16);
        if (m == 0) g_partial[blockIdx.x] = Sm;
    }

    // ---- last-block final reduction (deterministic) ----
    if (tid == 0) {
        __threadfence();
        unsigned int ticket = atomicAdd(&g_count, 1u);
        s->done = (ticket == NBLK - 1) ? 1 : 0;
    }
    __syncthreads();
    if (s->done) {
        __threadfence();
        float sum = 0.f;
        for (int i = tid; i < NBLK; i += NTH) sum += g_partial[i];
        #pragma unroll
        for (int off = 16; off; off >>= 1) sum += __shfl_down_sync(0xffffffffu, sum, off);
        if (lane == 0) s->warp_s[wid] = sum;
        __syncthreads();
        if (tid < 32) {
            sum = (lane < 8) ? s->warp_s[lane] : 0.f;
            #pragma unroll
            for (int off = 4; off; off >>= 1) sum += __shfl_down_sync(0xffffffffu, sum, off);
            if (lane == 0) {
                out[0] = sum / (float)NPTS;
                g_count = 0;
            }
        }
    }
}

extern "C" void kernel_launch(void* const* d_in, const int* in_sizes, int n_in,
                              void* d_out, int out_size) {
    const float* coords = (const float*)d_in[0];
    const float* W1     = (const float*)d_in[1];
    const float* b1     = (const float*)d_in[2];
    const float* W2     = (const float*)d_in[3];
    const float* b2     = (const float*)d_in[4];
    const float* W3     = (const float*)d_in[5];
    const float* b3     = (const float*)d_in[6];
    const float* W4     = (const float*)d_in[7];
    const float* b4     = (const float*)d_in[8];
    const float* wts    = (const float*)d_in[9];

    prep_kernel<<<dim3(8, 8, 2), dim3(32, 8)>>>(W2, W3);

    const size_t smem_bytes = sizeof(Smem);
    cudaFuncSetAttribute(mhd_kernel, cudaFuncAttributeMaxDynamicSharedMemorySize,
                         (int)smem_bytes);
    mhd_kernel<<<NBLK, NTH, smem_bytes>>>(coords, W1, b1, b2, b3, W4, b4, wts,
                                          (float*)d_out);
}

// round 12
// speedup vs baseline: 3.1959x; 1.3655x over previous
#include <cuda_runtime.h>
#include <cuda_fp16.h>
#include <math.h>
#include <stdint.h>

#define NPTS     131072
#define HDIM     256
#define PTS      16              // points per CTA
#define NTH      256             // 8 warps, 2x4 grid
#define NBLK     (NPTS / PTS)    // 8192
#define AP       264             // A smem pitch (halfs): 528B, conflict-free ldmatrix
#define KCH      64              // K chunk
#define NCH      (HDIM / KCH)    // 4
#define BTILEB   32768           // bytes per B tile (256 n x 64 k x 2B)
#define GAMMA_F  (5.0f / 3.0f)

__device__ __align__(16) __half g_Wt[2][HDIM * HDIM];  // [layer][n*256+k] fp16
__device__ float g_partial[NBLK];
__device__ unsigned int g_count = 0;

struct __align__(16) Smem {
    __half A[64 * AP];              // 33792 B   rows: v*16 + p
    __half Wb[2][HDIM * KCH];       // 65536 B   [buf] swizzled; aliased as sd in epilogue
    float bias_s[HDIM];
    float W1s[3][HDIM];
    float W4Ts[6][HDIM];
    float OUT[4][PTS][6];
    float coords[PTS][3];
    float b4s[6];
    float warp_s[8];
    int   done;
};

// ---------------- asm helpers (baseline sm_80+ PTX only) ----------------
__device__ __forceinline__ uint32_t smem_u32(const void* p) {
    uint32_t a;
    asm("{ .reg .u64 t; cvta.to.shared.u64 t, %1; cvt.u32.u64 %0, t; }" : "=r"(a) : "l"(p));
    return a;
}
#define CP_ASYNC16(dst, src) \
    asm volatile("cp.async.cg.shared.global [%0], [%1], 16;" :: "r"(dst), "l"(src))
#define CP_COMMIT()  asm volatile("cp.async.commit_group;" ::: "memory")
#define CP_WAIT0()   asm volatile("cp.async.wait_group 0;" ::: "memory")

#define LDSM4(r0, r1, r2, r3, addr) \
    asm volatile("ldmatrix.sync.aligned.m8n8.x4.shared.b16 {%0,%1,%2,%3}, [%4];" \
                 : "=r"(r0), "=r"(r1), "=r"(r2), "=r"(r3) : "r"(addr))

#define MMAF16(d, a, b0, b1) \
    asm volatile("mma.sync.aligned.m16n8k16.row.col.f32.f16.f16.f32 " \
                 "{%0,%1,%2,%3}, {%4,%5,%6,%7}, {%8,%9}, {%0,%1,%2,%3};" \
                 : "+f"((d)[0]), "+f"((d)[1]), "+f"((d)[2]), "+f"((d)[3]) \
                 : "r"((a)[0]), "r"((a)[1]), "r"((a)[2]), "r"((a)[3]), \
                   "r"(b0), "r"(b1))

// B tile: 256 rows x 128B. (n, kbyte 0..112 step 16) -> n*128 + (kb ^ ((n&7)<<4)).
// 8 consecutive n at fixed kb -> 8 distinct 16B slots (ldmatrix conflict-free);
// one row per 8-lane cp.async phase -> contiguous 128B (store conflict-free).
__device__ __forceinline__ uint32_t btile_off(uint32_t n, uint32_t kbyte) {
    return n * 128u + (kbyte ^ ((n & 7u) << 4));
}

// ---------------- prep: W2/W3 fp32 [k][n] -> g_Wt[L][n][k] fp16 ----------------
__global__ void prep_kernel(const float* __restrict__ W2, const float* __restrict__ W3) {
    __shared__ float t[32][33];
    const float* W = blockIdx.z ? W3 : W2;
    const int tx = threadIdx.x, ty = threadIdx.y;
    const int bx = blockIdx.x, by = blockIdx.y, L = blockIdx.z;
    #pragma unroll
    for (int i = 0; i < 4; i++) {
        int lk = ty + i * 8;
        t[lk][tx] = W[(by * 32 + lk) * HDIM + bx * 32 + tx];
    }
    __syncthreads();
    #pragma unroll
    for (int i = 0; i < 4; i++) {
        int ln = ty + i * 8;
        int n = bx * 32 + ln;
        int k = by * 32 + tx;
        g_Wt[L][n * HDIM + k] = __float2half_rn(t[tx][ln]);
    }
}

// ---------------- main fused kernel ----------------
__global__ void __launch_bounds__(NTH, 2)
mhd_kernel(const float* __restrict__ coords,
           const float* __restrict__ W1, const float* __restrict__ b1,
           const float* __restrict__ b2, const float* __restrict__ b3,
           const float* __restrict__ W4, const float* __restrict__ b4,
           const float* __restrict__ wts, float* __restrict__ out) {
    extern __shared__ char raw[];
    Smem* s = (Smem*)raw;
    const int tid = threadIdx.x, wid = tid >> 5, lane = tid & 31;
    const int wm = wid >> 2, wn = wid & 3;         // 2x4 warp grid (M=64, N=256)
    const int gid = lane >> 2, tig = lane & 3;     // fragment coords

    const uint32_t a_b  = smem_u32(s->A);
    const uint32_t wb_b = smem_u32(s->Wb);
    __half* sdbuf = (__half*)s->Wb;                // epilogue alias: sd[p*AP+n]

    // ---- stage constants ----
    for (int i = tid; i < 3 * HDIM; i += NTH) ((float*)s->W1s)[i] = W1[i];
    for (int i = tid; i < 6 * HDIM; i += NTH) {
        int k = i / 6, j = i % 6;
        s->W4Ts[j][k] = W4[i];
    }
    if (tid < PTS * 3) ((float*)s->coords)[tid] = coords[blockIdx.x * PTS * 3 + tid];
    if (tid < 6) s->b4s[tid] = b4[tid];
    __syncthreads();

    // ---- layer 1: 3 -> 256, seed A rows v*16+p ----
    #pragma unroll
    for (int i = 0; i < 8; i++) {
        int idx = tid + i * NTH;                 // 0..2047
        int p = idx >> 7, n = (idx & 127) * 2;
        float w00 = s->W1s[0][n], w01 = s->W1s[0][n + 1];
        float w10 = s->W1s[1][n], w11 = s->W1s[1][n + 1];
        float w20 = s->W1s[2][n], w21 = s->W1s[2][n + 1];
        float c0 = s->coords[p][0], c1 = s->coords[p][1], c2 = s->coords[p][2];
        float z0 = fmaf(c2, w20, fmaf(c1, w10, fmaf(c0, w00, b1[n])));
        float z1 = fmaf(c2, w21, fmaf(c1, w11, fmaf(c0, w01, b1[n + 1])));
        float h0 = tanhf(z0), h1 = tanhf(z1);
        float sd0 = 1.f - h0 * h0, sd1 = 1.f - h1 * h1;
        *(__half2*)&s->A[p * AP + n]        = __floats2half2_rn(h0, h1);
        *(__half2*)&s->A[(16 + p) * AP + n] = __floats2half2_rn(sd0 * w00, sd1 * w01);
        *(__half2*)&s->A[(32 + p) * AP + n] = __floats2half2_rn(sd0 * w10, sd1 * w11);
        *(__half2*)&s->A[(48 + p) * AP + n] = __floats2half2_rn(sd0 * w20, sd1 * w21);
    }
    __syncthreads();

    // per-lane ldmatrix address components
    const uint32_t a_row = (uint32_t)(wm * 32 + (lane & 15));
    const uint32_t a_colsel = (uint32_t)((lane >> 4) << 3);
    const uint32_t b_ln = (uint32_t)(wn * 64 + (lane & 7) + ((lane >> 4) << 3));
    const uint32_t b_ksel16 = (uint32_t)(((lane >> 3) & 1) << 4);
    const uint32_t b_xor = (b_ln & 7u) << 4;
    const uint32_t b_base = b_ln * 128u;           // np step: +2048B (xor invariant)

    // ---- layers 2 & 3: pipelined single-sweep fp16 HMMA ----
    const float* biases[2] = {b2, b3};
    for (int L = 0; L < 2; L++) {
        s->bias_s[tid] = biases[L][tid];

        auto load_chunk = [&](int buf, int kb) {
            #pragma unroll
            for (int i = 0; i < 8; i++) {
                int id = tid + i * NTH;            // 0..2047
                int n = id >> 3, ks = id & 7;
                const __half* src = &g_Wt[L][n * HDIM + kb + ks * 8];
                uint32_t dst = wb_b + (uint32_t)(buf * BTILEB)
                             + btile_off((uint32_t)n, (uint32_t)(ks * 16));
                CP_ASYNC16(dst, (const void*)src);
            }
            CP_COMMIT();
        };

        load_chunk(0, 0);

        float acc[2][8][4];
        #pragma unroll
        for (int mt = 0; mt < 2; mt++)
            #pragma unroll
            for (int nt = 0; nt < 8; nt++)
                #pragma unroll
                for (int e = 0; e < 4; e++) acc[mt][nt][e] = 0.f;

        for (int c = 0; c < NCH; c++) {
            CP_WAIT0();
            __syncthreads();
            if (c + 1 < NCH) load_chunk((c + 1) & 1, (c + 1) * KCH);
            const uint32_t wcur = wb_b + (uint32_t)((c & 1) * BTILEB);

            #pragma unroll
            for (int kk = 0; kk < 4; kk++) {       // four k16 steps per chunk
                const uint32_t a_off = (a_row * AP + (uint32_t)(c * KCH + kk * 16) + a_colsel) * 2u;
                uint32_t ah[2][4];
                LDSM4(ah[0][0], ah[0][1], ah[0][2], ah[0][3], a_b + a_off);
                LDSM4(ah[1][0], ah[1][1], ah[1][2], ah[1][3], a_b + a_off + 16u * AP * 2u);

                const uint32_t bco = b_base + (((uint32_t)(kk * 32) + b_ksel16) ^ b_xor);
                #pragma unroll
                for (int nh = 0; nh < 2; nh++) {
                    uint32_t bh[2][4];
                    LDSM4(bh[0][0], bh[0][1], bh[0][2], bh[0][3],
                          wcur + bco + (uint32_t)((nh * 2 + 0) * 2048));
                    LDSM4(bh[1][0], bh[1][1], bh[1][2], bh[1][3],
                          wcur + bco + (uint32_t)((nh * 2 + 1) * 2048));
                    #pragma unroll
                    for (int mt = 0; mt < 2; mt++)
                        #pragma unroll
                        for (int ntl = 0; ntl < 4; ntl++)
                            MMAF16(acc[mt][nh * 4 + ntl], ah[mt],
                                   bh[ntl >> 1][(ntl & 1) * 2], bh[ntl >> 1][(ntl & 1) * 2 + 1]);
                }
            }
        }
        __syncthreads();   // MMAs done; Wb free -> sd alias

        // ---- epilogue: primal tile (wm=0, mt=0) tanh + sd; others scale ----
        if (wm == 0) {
            #pragma unroll
            for (int nt = 0; nt < 8; nt++) {
                int nb = wn * 64 + nt * 8 + 2 * tig;
                #pragma unroll
                for (int eh = 0; eh < 2; eh++) {
                    int p = gid + eh * 8;
                    float z0 = acc[0][nt][eh * 2]     + s->bias_s[nb];
                    float z1 = acc[0][nt][eh * 2 + 1] + s->bias_s[nb + 1];
                    float h0 = tanhf(z0), h1 = tanhf(z1);
                    *(__half2*)&s->A[p * AP + nb] = __floats2half2_rn(h0, h1);
                    *(__half2*)&sdbuf[p * AP + nb] =
                        __floats2half2_rn(1.f - h0 * h0, 1.f - h1 * h1);
                }
            }
        }
        __syncthreads();
        #pragma unroll
        for (int mt = 0; mt < 2; mt++) {
            if (wm == 0 && mt == 0) continue;        // primal already written
            #pragma unroll
            for (int nt = 0; nt < 8; nt++) {
                int nb = wn * 64 + nt * 8 + 2 * tig;
                #pragma unroll
                for (int eh = 0; eh < 2; eh++) {
                    int p = gid + eh * 8;
                    int r = wm * 32 + mt * 16 + p;
                    __half2 sd2 = *(__half2*)&sdbuf[p * AP + nb];
                    float v0 = acc[mt][nt][eh * 2]     * __half2float(sd2.x);
                    float v1 = acc[mt][nt][eh * 2 + 1] * __half2float(sd2.y);
                    *(__half2*)&s->A[r * AP + nb] = __floats2half2_rn(v0, v1);
                }
            }
        }
        __syncthreads();   // sd reads done; next layer may overwrite Wb
    }

    // ---- layer 4: 256 -> 6, k-split over 4 threads per row ----
    {
        int row = tid >> 2;                        // 0..63 = v*16+p
        int ks = tid & 3;
        float acc4[6] = {0.f, 0.f, 0.f, 0.f, 0.f, 0.f};
        #pragma unroll 8
        for (int k = ks * 64; k < ks * 64 + 64; k++) {
            float a = __half2float(s->A[row * AP + k]);
            #pragma unroll
            for (int j = 0; j < 6; j++)
                acc4[j] = fmaf(a, s->W4Ts[j][k], acc4[j]);
        }
        #pragma unroll
        for (int j = 0; j < 6; j++) {
            acc4[j] += __shfl_down_sync(0xffffffffu, acc4[j], 2, 4);
            acc4[j] += __shfl_down_sync(0xffffffffu, acc4[j], 1, 4);
        }
        if (ks == 0) {
            int v = row >> 4, p = row & 15;
            #pragma unroll
            for (int j = 0; j < 6; j++)
                s->OUT[v][p][j] = acc4[j] + ((v == 0) ? s->b4s[j] : 0.f);
        }
    }
    __syncthreads();

    // ---- residuals + reduction over the CTA's 16 points ----
    if (tid < PTS) {
        const int m = tid;
        const float* P  = s->OUT[0][m];
        const float* Jx = s->OUT[1][m];
        const float* Jy = s->OUT[2][m];
        const float* Jt = s->OUT[3][m];
        const float rho = P[0], vx = P[1], vy = P[2], Bx = P[3], By = P[4], Pp = P[5];
        const float ig = 1.f / (GAMMA_F - 1.f);

        const float dt_rho = Jt[0], dt_Bx = Jt[3], dt_By = Jt[4];
        const float dt_rhovx = dt_rho * vx + rho * Jt[1];
        const float dt_rhovy = dt_rho * vy + rho * Jt[2];

        #define DE(Jc) ((Jc)[5] * ig + 0.5f * (Jc)[0] * (vx * vx + vy * vy) \
                        + rho * (vx * (Jc)[1] + vy * (Jc)[2]) + Bx * (Jc)[3] + By * (Jc)[4])
        #define DG(Jc) ((Jc)[1] * By + vx * (Jc)[4] - (Jc)[2] * Bx - vy * (Jc)[3])
        #define DD(Jc) ((Jc)[3] * vx + Bx * (Jc)[1] + (Jc)[4] * vy + By * (Jc)[2])

        const float dE_dx = DE(Jx), dE_dy = DE(Jy), dE_dt = DE(Jt);
        const float div_v = Jx[1] + Jy[2];
        const float div_B = Jx[3] + Jy[4];
        const float continuity = dt_rho + rho * div_v;
        const float dPm_dx = Jx[5] + Bx * Jx[3] + By * Jx[4];
        const float dPm_dy = Jy[5] + Bx * Jy[3] + By * Jy[4];
        const float momentum_x = dt_rhovx + dPm_dx - (Bx * Jx[3] + By * Jy[3]);
        const float momentum_y = dt_rhovy + dPm_dy - (Bx * Jx[4] + By * Jy[4]);
        const float induction_x = dt_Bx + DG(Jy);
        const float induction_y = dt_By - DG(Jx);
        const float Ee = Pp * ig + 0.5f * rho * (vx * vx + vy * vy) + 0.5f * (Bx * Bx + By * By);
        const float S  = Ee + Pp + 0.5f * (Bx * Bx + By * By);
        const float dS_dx = dE_dx + Jx[5] + Bx * Jx[3] + By * Jx[4];
        const float dS_dy = dE_dy + Jy[5] + Bx * Jy[3] + By * Jy[4];
        const float D = Bx * vx + By * vy;
        const float dFx_dx = dS_dx * vx + S * Jx[1] - DD(Jx) * Bx - D * Jx[3];
        const float dFy_dy = dS_dy * vy + S * Jy[2] - DD(Jy) * By - D * Jy[4];
        const float energy = dE_dt + dFx_dx + dFy_dy;

        float Sm = wts[0] * continuity * continuity
                 + wts[1] * momentum_x * momentum_x
                 + wts[2] * momentum_y * momentum_y
                 + wts[3] * induction_x * induction_x
                 + wts[4] * induction_y * induction_y
                 + wts[5] * energy * energy
                 + wts[6] * div_B * div_B;

        #pragma unroll
        for (int off = 8; off; off >>= 1)
            Sm += __shfl_down_sync(0x0000ffffu, Sm, off, 16);
        if (m == 0) g_partial[blockIdx.x] = Sm;
    }

    // ---- last-block final reduction (deterministic) ----
    if (tid == 0) {
        __threadfence();
        unsigned int ticket = atomicAdd(&g_count, 1u);
        s->done = (ticket == NBLK - 1) ? 1 : 0;
    }
    __syncthreads();
    if (s->done) {
        __threadfence();
        float sum = 0.f;
        for (int i = tid; i < NBLK; i += NTH) sum += g_partial[i];
        #pragma unroll
        for (int off = 16; off; off >>= 1) sum += __shfl_down_sync(0xffffffffu, sum, off);
        if (lane == 0) s->warp_s[wid] = sum;
        __syncthreads();
        if (tid < 32) {
            sum = (lane < 8) ? s->warp_s[lane] : 0.f;
            #pragma unroll
            for (int off = 4; off; off >>= 1) sum += __shfl_down_sync(0xffffffffu, sum, off);
            if (lane == 0) {
                out[0] = sum / (float)NPTS;
                g_count = 0;
            }
        }
    }
}

extern "C" void kernel_launch(void* const* d_in, const int* in_sizes, int n_in,
                              void* d_out, int out_size) {
    const float* coords = (const float*)d_in[0];
    const float* W1     = (const float*)d_in[1];
    const float* b1     = (const float*)d_in[2];
    const float* W2     = (const float*)d_in[3];
    const float* b2     = (const float*)d_in[4];
    const float* W3     = (const float*)d_in[5];
    const float* b3     = (const float*)d_in[6];
    const float* W4     = (const float*)d_in[7];
    const float* b4     = (const float*)d_in[8];
    const float* wts    = (const float*)d_in[9];

    prep_kernel<<<dim3(8, 8, 2), dim3(32, 8)>>>(W2, W3);

    const size_t smem_bytes = sizeof(Smem);
    cudaFuncSetAttribute(mhd_kernel, cudaFuncAttributeMaxDynamicSharedMemorySize,
                         (int)smem_bytes);
    mhd_kernel<<<NBLK, NTH, smem_bytes>>>(coords, W1, b1, b2, b3, W4, b4, wts,
                                          (float*)d_out);
}

// round 13
// speedup vs baseline: 3.7450x; 1.1718x over previous
#include <cuda_runtime.h>
#include <cuda_fp16.h>
#include <math.h>
#include <stdint.h>

#define NPTS     131072
#define HDIM     256
#define PTS      16              // points per CTA
#define NTH      256             // 8 warps, 1x8 grid (M=64 all, N=32 per warp)
#define NBLK     (NPTS / PTS)    // 8192
#define AP       264             // A smem pitch (halfs): 528B, conflict-free ldmatrix
#define GAMMA_F  (5.0f / 3.0f)

// Fragment-ready W: [t = L*16+ks][g=0..15][lane=0..31] -> uint4 (16B)
// lane's uint4 = {nt0.b0, nt0.b1, nt1.b0, nt1.b1} for n-tiles 2g, 2g+1 (ntX: n = X*8 + l>>2)
__device__ __align__(16) uint4 g_Wf[32 * 16 * 32];
__device__ float g_partial[NBLK];
__device__ unsigned int g_count = 0;

struct __align__(16) Smem {
    __half A[64 * AP];              // 33792 B   rows: v*16 + p
    float bias_s[HDIM];
    float W1s[3][HDIM];
    float W4Ts[6][HDIM];
    float OUT[4][PTS][6];
    float coords[PTS][3];
    float b4s[6];
    float warp_s[8];
    int   done;
};

// ---------------- asm helpers (baseline sm_80+ PTX only) ----------------
__device__ __forceinline__ uint32_t smem_u32(const void* p) {
    uint32_t a;
    asm("{ .reg .u64 t; cvta.to.shared.u64 t, %1; cvt.u32.u64 %0, t; }" : "=r"(a) : "l"(p));
    return a;
}
#define LDSM4(r0, r1, r2, r3, addr) \
    asm volatile("ldmatrix.sync.aligned.m8n8.x4.shared.b16 {%0,%1,%2,%3}, [%4];" \
                 : "=r"(r0), "=r"(r1), "=r"(r2), "=r"(r3) : "r"(addr))

#define MMAF16(d, a, b0, b1) \
    asm volatile("mma.sync.aligned.m16n8k16.row.col.f32.f16.f16.f32 " \
                 "{%0,%1,%2,%3}, {%4,%5,%6,%7}, {%8,%9}, {%0,%1,%2,%3};" \
                 : "+f"((d)[0]), "+f"((d)[1]), "+f"((d)[2]), "+f"((d)[3]) \
                 : "r"((a)[0]), "r"((a)[1]), "r"((a)[2]), "r"((a)[3]), \
                   "r"(b0), "r"(b1))

// ---------------- prep: W2/W3 fp32 [k][n] -> fragment-ready fp16 ----------------
// thread id -> (t, g, lane); 64 blocks x 256 threads = 16384 = 32*16*32
__global__ void prep_kernel(const float* __restrict__ W2, const float* __restrict__ W3) {
    int id = blockIdx.x * blockDim.x + threadIdx.x;      // 0..16383
    int l  = id & 31;
    int g  = (id >> 5) & 15;
    int t  = id >> 9;                                    // 0..31
    const float* W = (t >= 16) ? W3 : W2;
    int ks = t & 15;
    int n0 = g * 16 + (l >> 2);
    int n1 = n0 + 8;
    int kb = ks * 16 + 2 * (l & 3);

    __half2 x = __floats2half2_rn(W[kb * HDIM + n0],       W[(kb + 1) * HDIM + n0]);
    __half2 y = __floats2half2_rn(W[(kb + 8) * HDIM + n0], W[(kb + 9) * HDIM + n0]);
    __half2 z = __floats2half2_rn(W[kb * HDIM + n1],       W[(kb + 1) * HDIM + n1]);
    __half2 w = __floats2half2_rn(W[(kb + 8) * HDIM + n1], W[(kb + 9) * HDIM + n1]);

    uint4 v;
    v.x = *(uint32_t*)&x; v.y = *(uint32_t*)&y;
    v.z = *(uint32_t*)&z; v.w = *(uint32_t*)&w;
    g_Wf[((t * 16) + g) * 32 + l] = v;
}

// ---------------- main fused kernel ----------------
__global__ void __launch_bounds__(NTH, 2)
mhd_kernel(const float* __restrict__ coords,
           const float* __restrict__ W1, const float* __restrict__ b1,
           const float* __restrict__ b2, const float* __restrict__ b3,
           const float* __restrict__ W4, const float* __restrict__ b4,
           const float* __restrict__ wts, float* __restrict__ out) {
    extern __shared__ char raw[];
    Smem* s = (Smem*)raw;
    const int tid = threadIdx.x, wid = tid >> 5, lane = tid & 31;
    const int gid = lane >> 2, tig = lane & 3;     // fragment coords

    const uint32_t a_b = smem_u32(s->A);

    // ---- stage constants ----
    for (int i = tid; i < 3 * HDIM; i += NTH) ((float*)s->W1s)[i] = W1[i];
    for (int i = tid; i < 6 * HDIM; i += NTH) {
        int k = i / 6, j = i % 6;
        s->W4Ts[j][k] = W4[i];
    }
    if (tid < PTS * 3) ((float*)s->coords)[tid] = coords[blockIdx.x * PTS * 3 + tid];
    if (tid < 6) s->b4s[tid] = b4[tid];
    __syncthreads();

    // ---- layer 1: 3 -> 256, seed A rows v*16+p ----
    #pragma unroll
    for (int i = 0; i < 8; i++) {
        int idx = tid + i * NTH;                 // 0..2047
        int p = idx >> 7, n = (idx & 127) * 2;
        float w00 = s->W1s[0][n], w01 = s->W1s[0][n + 1];
        float w10 = s->W1s[1][n], w11 = s->W1s[1][n + 1];
        float w20 = s->W1s[2][n], w21 = s->W1s[2][n + 1];
        float c0 = s->coords[p][0], c1 = s->coords[p][1], c2 = s->coords[p][2];
        float z0 = fmaf(c2, w20, fmaf(c1, w10, fmaf(c0, w00, b1[n])));
        float z1 = fmaf(c2, w21, fmaf(c1, w11, fmaf(c0, w01, b1[n + 1])));
        float h0 = tanhf(z0), h1 = tanhf(z1);
        float sd0 = 1.f - h0 * h0, sd1 = 1.f - h1 * h1;
        *(__half2*)&s->A[p * AP + n]        = __floats2half2_rn(h0, h1);
        *(__half2*)&s->A[(16 + p) * AP + n] = __floats2half2_rn(sd0 * w00, sd1 * w01);
        *(__half2*)&s->A[(32 + p) * AP + n] = __floats2half2_rn(sd0 * w10, sd1 * w11);
        *(__half2*)&s->A[(48 + p) * AP + n] = __floats2half2_rn(sd0 * w20, sd1 * w21);
    }
    __syncthreads();

    // per-lane A ldmatrix address components
    const uint32_t a_rowsel = (uint32_t)(lane & 15);
    const uint32_t a_colsel = (uint32_t)((lane >> 4) << 3);

    // B fragment pointer for this warp: groups wid*2, wid*2+1
    const uint4* wf = &g_Wf[(size_t)(wid * 2) * 32 + lane];

    // ---- layers 2 & 3: LDG-fragment fp16 HMMA, no smem for W ----
    const float* biases[2] = {b2, b3};
    uint4 bc0 = wf[0], bc1 = wf[32];               // t = 0 prefetched

    for (int L = 0; L < 2; L++) {
        s->bias_s[tid] = biases[L][tid];

        float acc[4][4][4];
        #pragma unroll
        for (int mt = 0; mt < 4; mt++)
            #pragma unroll
            for (int nt = 0; nt < 4; nt++)
                #pragma unroll
                for (int e = 0; e < 4; e++) acc[mt][nt][e] = 0.f;

        #pragma unroll 4
        for (int ks = 0; ks < 16; ks++) {
            const int t = L * 16 + ks;
            uint4 bn0, bn1;
            if (t + 1 < 32) {
                bn0 = wf[(size_t)(t + 1) * 16 * 32];
                bn1 = wf[(size_t)(t + 1) * 16 * 32 + 32];
            }
            uint32_t a[4][4];
            #pragma unroll
            for (int mt = 0; mt < 4; mt++) {
                uint32_t off = ((uint32_t)(mt * 16) + a_rowsel) * AP * 2u
                             + ((uint32_t)(ks * 16) + a_colsel) * 2u;
                LDSM4(a[mt][0], a[mt][1], a[mt][2], a[mt][3], a_b + off);
            }
            #pragma unroll
            for (int mt = 0; mt < 4; mt++) {
                MMAF16(acc[mt][0], a[mt], bc0.x, bc0.y);
                MMAF16(acc[mt][1], a[mt], bc0.z, bc0.w);
                MMAF16(acc[mt][2], a[mt], bc1.x, bc1.y);
                MMAF16(acc[mt][3], a[mt], bc1.z, bc1.w);
            }
            bc0 = bn0; bc1 = bn1;
        }
        __syncthreads();   // all A (old) reads complete

        // ---- epilogue: sd stays in-thread (acc[0] and acc[mt] share (p,n) map) ----
        #pragma unroll
        for (int nt = 0; nt < 4; nt++) {
            int nb = wid * 32 + nt * 8 + 2 * tig;
            float bs0 = s->bias_s[nb], bs1 = s->bias_s[nb + 1];
            #pragma unroll
            for (int eh = 0; eh < 2; eh++) {
                int p = gid + eh * 8;
                float h0 = tanhf(acc[0][nt][eh * 2]     + bs0);
                float h1 = tanhf(acc[0][nt][eh * 2 + 1] + bs1);
                float sd0 = 1.f - h0 * h0, sd1 = 1.f - h1 * h1;
                *(__half2*)&s->A[p * AP + nb] = __floats2half2_rn(h0, h1);
                #pragma unroll
                for (int mt = 1; mt < 4; mt++) {
                    *(__half2*)&s->A[(mt * 16 + p) * AP + nb] =
                        __floats2half2_rn(acc[mt][nt][eh * 2] * sd0,
                                          acc[mt][nt][eh * 2 + 1] * sd1);
                }
            }
        }
        __syncthreads();   // new A visible before next layer / layer 4
    }

    // ---- layer 4: 256 -> 6, k-split over 4 threads per row ----
    {
        int row = tid >> 2;                        // 0..63 = v*16+p
        int ks = tid & 3;
        float acc4[6] = {0.f, 0.f, 0.f, 0.f, 0.f, 0.f};
        #pragma unroll 8
        for (int k = ks * 64; k < ks * 64 + 64; k++) {
            float a = __half2float(s->A[row * AP + k]);
            #pragma unroll
            for (int j = 0; j < 6; j++)
                acc4[j] = fmaf(a, s->W4Ts[j][k], acc4[j]);
        }
        #pragma unroll
        for (int j = 0; j < 6; j++) {
            acc4[j] += __shfl_down_sync(0xffffffffu, acc4[j], 2, 4);
            acc4[j] += __shfl_down_sync(0xffffffffu, acc4[j], 1, 4);
        }
        if (ks == 0) {
            int v = row >> 4, p = row & 15;
            #pragma unroll
            for (int j = 0; j < 6; j++)
                s->OUT[v][p][j] = acc4[j] + ((v == 0) ? s->b4s[j] : 0.f);
        }
    }
    __syncthreads();

    // ---- residuals + reduction over the CTA's 16 points ----
    if (tid < PTS) {
        const int m = tid;
        const float* P  = s->OUT[0][m];
        const float* Jx = s->OUT[1][m];
        const float* Jy = s->OUT[2][m];
        const float* Jt = s->OUT[3][m];
        const float rho = P[0], vx = P[1], vy = P[2], Bx = P[3], By = P[4], Pp = P[5];
        const float ig = 1.f / (GAMMA_F - 1.f);

        const float dt_rho = Jt[0], dt_Bx = Jt[3], dt_By = Jt[4];
        const float dt_rhovx = dt_rho * vx + rho * Jt[1];
        const float dt_rhovy = dt_rho * vy + rho * Jt[2];

        #define DE(Jc) ((Jc)[5] * ig + 0.5f * (Jc)[0] * (vx * vx + vy * vy) \
                        + rho * (vx * (Jc)[1] + vy * (Jc)[2]) + Bx * (Jc)[3] + By * (Jc)[4])
        #define DG(Jc) ((Jc)[1] * By + vx * (Jc)[4] - (Jc)[2] * Bx - vy * (Jc)[3])
        #define DD(Jc) ((Jc)[3] * vx + Bx * (Jc)[1] + (Jc)[4] * vy + By * (Jc)[2])

        const float dE_dx = DE(Jx), dE_dy = DE(Jy), dE_dt = DE(Jt);
        const float div_v = Jx[1] + Jy[2];
        const float div_B = Jx[3] + Jy[4];
        const float continuity = dt_rho + rho * div_v;
        const float dPm_dx = Jx[5] + Bx * Jx[3] + By * Jx[4];
        const float dPm_dy = Jy[5] + Bx * Jy[3] + By * Jy[4];
        const float momentum_x = dt_rhovx + dPm_dx - (Bx * Jx[3] + By * Jy[3]);
        const float momentum_y = dt_rhovy + dPm_dy - (Bx * Jx[4] + By * Jy[4]);
        const float induction_x = dt_Bx + DG(Jy);
        const float induction_y = dt_By - DG(Jx);
        const float Ee = Pp * ig + 0.5f * rho * (vx * vx + vy * vy) + 0.5f * (Bx * Bx + By * By);
        const float S  = Ee + Pp + 0.5f * (Bx * Bx + By * By);
        const float dS_dx = dE_dx + Jx[5] + Bx * Jx[3] + By * Jx[4];
        const float dS_dy = dE_dy + Jy[5] + Bx * Jy[3] + By * Jy[4];
        const float D = Bx * vx + By * vy;
        const float dFx_dx = dS_dx * vx + S * Jx[1] - DD(Jx) * Bx - D * Jx[3];
        const float dFy_dy = dS_dy * vy + S * Jy[2] - DD(Jy) * By - D * Jy[4];
        const float energy = dE_dt + dFx_dx + dFy_dy;

        float Sm = wts[0] * continuity * continuity
                 + wts[1] * momentum_x * momentum_x
                 + wts[2] * momentum_y * momentum_y
                 + wts[3] * induction_x * induction_x
                 + wts[4] * induction_y * induction_y
                 + wts[5] * energy * energy
                 + wts[6] * div_B * div_B;

        #pragma unroll
        for (int off = 8; off; off >>= 1)
            Sm += __shfl_down_sync(0x0000ffffu, Sm, off, 16);
        if (m == 0) g_partial[blockIdx.x] = Sm;
    }

    // ---- last-block final reduction (deterministic) ----
    if (tid == 0) {
        __threadfence();
        unsigned int ticket = atomicAdd(&g_count, 1u);
        s->done = (ticket == NBLK - 1) ? 1 : 0;
    }
    __syncthreads();
    if (s->done) {
        __threadfence();
        float sum = 0.f;
        for (int i = tid; i < NBLK; i += NTH) sum += g_partial[i];
        #pragma unroll
        for (int off = 16; off; off >>= 1) sum += __shfl_down_sync(0xffffffffu, sum, off);
        if (lane == 0) s->warp_s[wid] = sum;
        __syncthreads();
        if (tid < 32) {
            sum = (lane < 8) ? s->warp_s[lane] : 0.f;
            #pragma unroll
            for (int off = 4; off; off >>= 1) sum += __shfl_down_sync(0xffffffffu, sum, off);
            if (lane == 0) {
                out[0] = sum / (float)NPTS;
                g_count = 0;
            }
        }
    }
}

extern "C" void kernel_launch(void* const* d_in, const int* in_sizes, int n_in,
                              void* d_out, int out_size) {
    const float* coords = (const float*)d_in[0];
    const float* W1     = (const float*)d_in[1];
    const float* b1     = (const float*)d_in[2];
    const float* W2     = (const float*)d_in[3];
    const float* b2     = (const float*)d_in[4];
    const float* W3     = (const float*)d_in[5];
    const float* b3     = (const float*)d_in[6];
    const float* W4     = (const float*)d_in[7];
    const float* b4     = (const float*)d_in[8];
    const float* wts    = (const float*)d_in[9];

    prep_kernel<<<64, 256>>>(W2, W3);

    const size_t smem_bytes = sizeof(Smem);
    cudaFuncSetAttribute(mhd_kernel, cudaFuncAttributeMaxDynamicSharedMemorySize,
                         (int)smem_bytes);
    mhd_kernel<<<NBLK, NTH, smem_bytes>>>(coords, W1, b1, b2, b3, W4, b4, wts,
                                          (float*)d_out);
}